// round 4
// baseline (speedup 1.0000x reference)
#include <cuda_runtime.h>
#include <cuda_bf16.h>
#include <math.h>

#define BQ 8
#define TQ 2048
#define DQ 512
#define NTOK (BQ * TQ)            // 16384
#define GRU_CTAS 128

// ---------------- scratch (device globals; allocation-free) ----------------
// Total ~368 MB (concat buffers eliminated via segment-aware GEMM loaders).
__device__ float g_short[NTOK * DQ];        // 32 MB
__device__ float g_mid[NTOK * DQ];          // 32 MB
__device__ float g_long[NTOK * DQ];         // 32 MB
__device__ float g_memc[NTOK * DQ];         // 32 MB
__device__ float g_change[NTOK * DQ];       // 32 MB
__device__ float g_fused[NTOK * DQ];        // 32 MB
__device__ float g_xg[NTOK * 3 * DQ];       // 96 MB
__device__ float g_h1[NTOK * 256];          // 16 MB
__device__ float g_fh[NTOK * 1024];         // 64 MB
__device__ float g_hbuf[2][BQ * DQ];
__device__ unsigned g_bar_count;
__device__ unsigned g_bar_sense;

struct SegPtrs { const float* p[5]; };

// ---------------- helpers ----------------
__device__ __forceinline__ float gelu_exact(float x) {
    return 0.5f * x * (1.0f + erff(x * 0.70710678118654752440f));
}

#define FMA2(d, a, b) asm("fma.rn.f32x2 %0, %1, %2, %0;" : "+l"(d) : "l"(a), "l"(b))

__device__ __forceinline__ unsigned long long pack2(float x, float y) {
    unsigned long long r;
    asm("mov.b64 %0, {%1, %2};" : "=l"(r) : "r"(__float_as_uint(x)), "r"(__float_as_uint(y)));
    return r;
}
__device__ __forceinline__ void unpack2(unsigned long long v, float& x, float& y) {
    unsigned lo, hi;
    asm("mov.b64 {%0, %1}, %2;" : "=r"(lo), "=r"(hi) : "l"(v));
    x = __uint_as_float(lo); y = __uint_as_float(hi);
}

__device__ __forceinline__ float block_sum_512(float v, float* red) {
    int lane = threadIdx.x & 31, w = threadIdx.x >> 5;
    #pragma unroll
    for (int off = 16; off > 0; off >>= 1) v += __shfl_xor_sync(0xffffffffu, v, off);
    if (lane == 0) red[w] = v;
    __syncthreads();
    float s = (threadIdx.x < 16) ? red[threadIdx.x] : 0.0f;
    if (w == 0) {
        #pragma unroll
        for (int off = 8; off > 0; off >>= 1) s += __shfl_xor_sync(0xffffffffu, s, off);
        if (lane == 0) red[0] = s;
    }
    __syncthreads();
    float r = red[0];
    __syncthreads();
    return r;
}

// ---------------- conv (3 scales) + per-scale LN, fused ----------------
__global__ void ctx_kernel(const float* __restrict__ emb,
                           const float* __restrict__ w_s, const float* __restrict__ b_s,
                           const float* __restrict__ g_s, const float* __restrict__ be_s,
                           const float* __restrict__ w_m, const float* __restrict__ b_m,
                           const float* __restrict__ g_m, const float* __restrict__ be_m,
                           const float* __restrict__ w_l, const float* __restrict__ b_l,
                           const float* __restrict__ g_l, const float* __restrict__ be_l,
                           float* __restrict__ out_s, float* __restrict__ out_m,
                           float* __restrict__ out_l) {
    __shared__ float red[16];
    const int token = blockIdx.x;
    const int t = token & (TQ - 1);
    const int d = threadIdx.x;

    float xr[32];
    #pragma unroll
    for (int j = 0; j < 32; j++)
        xr[j] = (t - j >= 0) ? emb[((size_t)(token - j)) * DQ + d] : 0.0f;

    float ys = b_s[d], ym = b_m[d], yl = b_l[d];
    #pragma unroll
    for (int j = 0; j < 2; j++)  ys += w_s[d * 2 + 1 - j] * xr[j];
    #pragma unroll
    for (int j = 0; j < 8; j++)  ym += w_m[d * 8 + 7 - j] * xr[j];
    #pragma unroll
    for (int j = 0; j < 32; j++) yl += w_l[d * 32 + 31 - j] * xr[j];

    const size_t base = (size_t)token * DQ + d;
    {
        float mu = block_sum_512(ys, red) * (1.0f / DQ);
        float dv = ys - mu;
        float var = block_sum_512(dv * dv, red) * (1.0f / DQ);
        out_s[base] = dv * rsqrtf(var + 1e-5f) * g_s[d] + be_s[d];
    }
    {
        float mu = block_sum_512(ym, red) * (1.0f / DQ);
        float dv = ym - mu;
        float var = block_sum_512(dv * dv, red) * (1.0f / DQ);
        out_m[base] = dv * rsqrtf(var + 1e-5f) * g_m[d] + be_m[d];
    }
    {
        float mu = block_sum_512(yl, red) * (1.0f / DQ);
        float dv = yl - mu;
        float var = block_sum_512(dv * dv, red) * (1.0f / DQ);
        out_l[base] = dv * rsqrtf(var + 1e-5f) * g_l[d] + be_l[d];
    }
}

// ---------------- GEMM core: 128x128x16 tile, 8x8/thread, f32x2 FMAs ----------
// As/Bs staged transposed; mainloop shared by both GEMM variants.
template <bool GELU>
__device__ __forceinline__ void gemm_core_epilogue(
    unsigned long long acc[8][4], const float* __restrict__ bias,
    float* __restrict__ C, int N, int m0, int n0, int tx, int ty) {
    #pragma unroll
    for (int i = 0; i < 8; i++) {
        const size_t m = m0 + ty * 8 + i;
        #pragma unroll
        for (int j = 0; j < 4; j++) {
            float v0, v1;
            unpack2(acc[i][j], v0, v1);
            int n = n0 + tx * 8 + j * 2;
            v0 += bias[n]; v1 += bias[n + 1];
            if (GELU) { v0 = gelu_exact(v0); v1 = gelu_exact(v1); }
            *reinterpret_cast<float2*>(&C[m * (size_t)N + n]) = make_float2(v0, v1);
        }
    }
}

__device__ __forceinline__ void gemm_mainloop_step(
    unsigned long long acc[8][4], const float As[16][128], const float Bs[16][128],
    int tx, int ty) {
    #pragma unroll
    for (int kk = 0; kk < 16; kk++) {
        float4 a0 = *reinterpret_cast<const float4*>(&As[kk][ty * 8]);
        float4 a1 = *reinterpret_cast<const float4*>(&As[kk][ty * 8 + 4]);
        ulonglong2 blo = *reinterpret_cast<const ulonglong2*>(&Bs[kk][tx * 8]);
        ulonglong2 bhi = *reinterpret_cast<const ulonglong2*>(&Bs[kk][tx * 8 + 4]);
        unsigned long long bv[4] = {blo.x, blo.y, bhi.x, bhi.y};
        unsigned long long av[8];
        av[0] = pack2(a0.x, a0.x); av[1] = pack2(a0.y, a0.y);
        av[2] = pack2(a0.z, a0.z); av[3] = pack2(a0.w, a0.w);
        av[4] = pack2(a1.x, a1.x); av[5] = pack2(a1.y, a1.y);
        av[6] = pack2(a1.z, a1.z); av[7] = pack2(a1.w, a1.w);
        #pragma unroll
        for (int i = 0; i < 8; i++)
            #pragma unroll
            for (int j = 0; j < 4; j++)
                FMA2(acc[i][j], av[i], bv[j]);
    }
}

// Plain GEMM: A contiguous (M,K). C[M,N] = A @ W[N,K]^T + bias (opt GELU).
template <bool GELU>
__global__ __launch_bounds__(256)
void gemm_kernel(const float* __restrict__ A, const float* __restrict__ W,
                 const float* __restrict__ bias, float* __restrict__ C,
                 int M, int N, int K) {
    __shared__ float As[16][128];
    __shared__ float Bs[16][128];
    const int tid = threadIdx.x;
    const int tx = tid & 15, ty = tid >> 4;
    const int m0 = blockIdx.y * 128, n0 = blockIdx.x * 128;

    unsigned long long acc[8][4];
    #pragma unroll
    for (int i = 0; i < 8; i++)
        #pragma unroll
        for (int j = 0; j < 4; j++) acc[i][j] = 0ull;

    for (int k0 = 0; k0 < K; k0 += 16) {
        #pragma unroll
        for (int v = 0; v < 2; v++) {
            int f = tid + v * 256;
            int r = f >> 2, c4 = (f & 3) << 2;
            float4 av = *reinterpret_cast<const float4*>(A + (size_t)(m0 + r) * K + k0 + c4);
            As[c4 + 0][r] = av.x; As[c4 + 1][r] = av.y;
            As[c4 + 2][r] = av.z; As[c4 + 3][r] = av.w;
            float4 bv = *reinterpret_cast<const float4*>(W + (size_t)(n0 + r) * K + k0 + c4);
            Bs[c4 + 0][r] = bv.x; Bs[c4 + 1][r] = bv.y;
            Bs[c4 + 2][r] = bv.z; Bs[c4 + 3][r] = bv.w;
        }
        __syncthreads();
        gemm_mainloop_step(acc, As, Bs, tx, ty);
        __syncthreads();
    }
    gemm_core_epilogue<GELU>(acc, bias, C, N, m0, n0, tx, ty);
}

// Segmented GEMM: logical A is a concat of 512-wide segments, gathered on the
// fly (no materialized concat buffer). seg = k0>>9 (BK=16 never straddles).
// PREV: segment 1 reads the previous token's row (t==0 clamps to itself).
template <bool GELU, bool PREV>
__global__ __launch_bounds__(256)
void seg_gemm_kernel(SegPtrs segs, const float* __restrict__ W,
                     const float* __restrict__ bias, float* __restrict__ C,
                     int M, int N, int K) {
    __shared__ float As[16][128];
    __shared__ float Bs[16][128];
    const int tid = threadIdx.x;
    const int tx = tid & 15, ty = tid >> 4;
    const int m0 = blockIdx.y * 128, n0 = blockIdx.x * 128;

    unsigned long long acc[8][4];
    #pragma unroll
    for (int i = 0; i < 8; i++)
        #pragma unroll
        for (int j = 0; j < 4; j++) acc[i][j] = 0ull;

    for (int k0 = 0; k0 < K; k0 += 16) {
        const int seg = k0 >> 9;
        const int ks = k0 & 511;
        const float* __restrict__ Aseg = segs.p[seg];
        #pragma unroll
        for (int v = 0; v < 2; v++) {
            int f = tid + v * 256;
            int r = f >> 2, c4 = (f & 3) << 2;
            int m = m0 + r;
            if (PREV && seg == 1) m = ((m & (TQ - 1)) == 0) ? m : m - 1;
            float4 av = *reinterpret_cast<const float4*>(Aseg + (size_t)m * DQ + ks + c4);
            As[c4 + 0][r] = av.x; As[c4 + 1][r] = av.y;
            As[c4 + 2][r] = av.z; As[c4 + 3][r] = av.w;
            float4 bv = *reinterpret_cast<const float4*>(W + (size_t)(n0 + r) * K + k0 + c4);
            Bs[c4 + 0][r] = bv.x; Bs[c4 + 1][r] = bv.y;
            Bs[c4 + 2][r] = bv.z; Bs[c4 + 3][r] = bv.w;
        }
        __syncthreads();
        gemm_mainloop_step(acc, As, Bs, tx, ty);
        __syncthreads();
    }
    gemm_core_epilogue<GELU>(acc, bias, C, N, m0, n0, tx, ty);
}

// ---------------- GRU persistent kernel ----------------
// 128 CTAs x 256 threads; CTA owns 4 state dims (12 W_hh rows); W_hh slice
// pinned in registers; h double-buffered in global; one grid barrier/step.
__global__ void __launch_bounds__(256)
gru_kernel(const float* __restrict__ xg, const float* __restrict__ W_hh,
           const float* __restrict__ b_hh, float* __restrict__ memc) {
    __shared__ float h_sh[BQ * DQ];
    __shared__ float hg_sh[BQ * 12];

    const int tid = threadIdx.x;
    const int w = tid >> 5, lane = tid & 31;
    const int bp = w & 1, rh = w >> 1;
    const int d0 = blockIdx.x * 4;

    unsigned long long wreg[3][8];
    #pragma unroll
    for (int rl = 0; rl < 3; rl++) {
        int lr = rh * 3 + rl;
        int grow = (lr >> 2) * DQ + d0 + (lr & 3);
        const float* wp = W_hh + (size_t)grow * DQ;
        #pragma unroll
        for (int j = 0; j < 8; j++) {
            float2 v = *reinterpret_cast<const float2*>(wp + j * 64 + lane * 2);
            wreg[rl][j] = pack2(v.x, v.y);
        }
    }

    for (int t = 0; t < TQ; t++) {
        const float* hin = g_hbuf[t & 1];
        float* hout = g_hbuf[(t + 1) & 1];

        const float4* hp = reinterpret_cast<const float4*>(hin);
        #pragma unroll
        for (int v = 0; v < 4; v++)
            reinterpret_cast<float4*>(h_sh)[tid + v * 256] = hp[tid + v * 256];

        float xr = 0.f, xz = 0.f, xn = 0.f;
        if (tid < 32) {
            int b = tid >> 2, i = tid & 3;
            size_t base = ((size_t)(b * TQ + t)) * (3 * DQ) + d0 + i;
            xr = xg[base];
            xz = xg[base + DQ];
            xn = xg[base + 2 * DQ];
        }
        __syncthreads();

        unsigned long long acc[3][4];
        #pragma unroll
        for (int rl = 0; rl < 3; rl++)
            #pragma unroll
            for (int bb = 0; bb < 4; bb++) acc[rl][bb] = 0ull;

        #pragma unroll
        for (int j = 0; j < 8; j++) {
            unsigned long long h2[4];
            #pragma unroll
            for (int bb = 0; bb < 4; bb++)
                h2[bb] = *reinterpret_cast<const unsigned long long*>(
                    &h_sh[(bp * 4 + bb) * DQ + j * 64 + lane * 2]);
            #pragma unroll
            for (int rl = 0; rl < 3; rl++)
                #pragma unroll
                for (int bb = 0; bb < 4; bb++)
                    FMA2(acc[rl][bb], h2[bb], wreg[rl][j]);
        }

        #pragma unroll
        for (int rl = 0; rl < 3; rl++)
            #pragma unroll
            for (int bb = 0; bb < 4; bb++) {
                float x, y;
                unpack2(acc[rl][bb], x, y);
                float s = x + y;
                #pragma unroll
                for (int off = 16; off > 0; off >>= 1)
                    s += __shfl_xor_sync(0xffffffffu, s, off);
                if (lane == 0) hg_sh[(bp * 4 + bb) * 12 + rh * 3 + rl] = s;
            }
        __syncthreads();

        if (tid < 32) {
            int b = tid >> 2, i = tid & 3;
            int d = d0 + i;
            float hr = hg_sh[b * 12 + i]     + b_hh[d];
            float hz = hg_sh[b * 12 + 4 + i] + b_hh[DQ + d];
            float hn = hg_sh[b * 12 + 8 + i] + b_hh[2 * DQ + d];
            float r = 1.0f / (1.0f + expf(-(xr + hr)));
            float z = 1.0f / (1.0f + expf(-(xz + hz)));
            float n = tanhf(xn + r * hn);
            float hold = h_sh[b * DQ + d];
            float hnew = (1.0f - z) * n + z * hold;
            hout[b * DQ + d] = hnew;
            memc[((size_t)(b * TQ + t)) * DQ + d] = hnew;
        }
        __syncthreads();

        if (tid == 0) {
            __threadfence();
            unsigned target = (unsigned)(t + 1) * GRU_CTAS;
            unsigned a = atomicAdd(&g_bar_count, 1u) + 1u;
            if (a == target) {
                atomicExch(&g_bar_sense, (unsigned)(t + 1));
            } else {
                volatile unsigned* vs = &g_bar_sense;
                int spins = 0;
                while (*vs < (unsigned)(t + 1)) {
                    if (++spins > 8) __nanosleep(64);
                }
            }
            __threadfence();
        }
        __syncthreads();
    }
}

__global__ void reset_kernel() {
    int tid = threadIdx.x;
    for (int i = tid; i < BQ * DQ; i += blockDim.x) {
        g_hbuf[0][i] = 0.0f;
        g_hbuf[1][i] = 0.0f;
    }
    if (tid == 0) { g_bar_count = 0u; g_bar_sense = 0u; }
}

// ---------------- final residual + LN ----------------
__global__ void final_kernel(const float* __restrict__ emb, const float* __restrict__ fused,
                             const float* __restrict__ change,
                             const float* __restrict__ ln_g, const float* __restrict__ ln_b,
                             float* __restrict__ out) {
    __shared__ float red[16];
    const int token = blockIdx.x;
    const int d = threadIdx.x;
    const size_t base = (size_t)token * DQ + d;
    float x = emb[base] + fused[base] + change[base];
    float mu = block_sum_512(x, red) * (1.0f / DQ);
    float dv = x - mu;
    float var = block_sum_512(dv * dv, red) * (1.0f / DQ);
    out[base] = dv * rsqrtf(var + 1e-5f) * ln_g[d] + ln_b[d];
}

// ---------------- launch ----------------
static float* symp(const void* sym) {
    void* p = nullptr;
    cudaGetSymbolAddress(&p, sym);
    return (float*)p;
}

extern "C" void kernel_launch(void* const* d_in, const int* in_sizes, int n_in,
                              void* d_out, int out_size) {
    const float* emb   = (const float*)d_in[0];
    const float* w_s   = (const float*)d_in[1];
    const float* b_s   = (const float*)d_in[2];
    const float* gs    = (const float*)d_in[3];
    const float* bes   = (const float*)d_in[4];
    const float* w_m   = (const float*)d_in[5];
    const float* b_m   = (const float*)d_in[6];
    const float* gm    = (const float*)d_in[7];
    const float* bem   = (const float*)d_in[8];
    const float* w_l   = (const float*)d_in[9];
    const float* b_l   = (const float*)d_in[10];
    const float* gl    = (const float*)d_in[11];
    const float* bel   = (const float*)d_in[12];
    const float* W_ih  = (const float*)d_in[13];
    const float* W_hh  = (const float*)d_in[14];
    const float* b_ih  = (const float*)d_in[15];
    const float* b_hh  = (const float*)d_in[16];
    const float* ce_w1 = (const float*)d_in[17];
    const float* ce_b1 = (const float*)d_in[18];
    const float* ce_w2 = (const float*)d_in[19];
    const float* ce_b2 = (const float*)d_in[20];
    const float* fu_w1 = (const float*)d_in[21];
    const float* fu_b1 = (const float*)d_in[22];
    const float* fu_w2 = (const float*)d_in[23];
    const float* fu_b2 = (const float*)d_in[24];
    const float* ln_g  = (const float*)d_in[25];
    const float* ln_b  = (const float*)d_in[26];

    float* sctx   = symp(g_short);
    float* mctx   = symp(g_mid);
    float* lctx   = symp(g_long);
    float* memc   = symp(g_memc);
    float* change = symp(g_change);
    float* fused  = symp(g_fused);
    float* xg     = symp(g_xg);
    float* h1     = symp(g_h1);
    float* fh     = symp(g_fh);

    // multi-scale conv + LN
    ctx_kernel<<<NTOK, 512>>>(emb, w_s, b_s, gs, bes, w_m, b_m, gm, bem,
                              w_l, b_l, gl, bel, sctx, mctx, lctx);

    // xg = emb @ W_ih^T + b_ih   (M=16384, N=1536, K=512)
    gemm_kernel<false><<<dim3(12, 128), 256>>>(emb, W_ih, b_ih, xg, NTOK, 1536, 512);

    // change path: h1 = gelu([emb, prev] @ ce_w1^T + b); change = h1 @ ce_w2^T + b
    {
        SegPtrs sp{};
        sp.p[0] = emb; sp.p[1] = emb;
        seg_gemm_kernel<true, true><<<dim3(2, 128), 256>>>(sp, ce_w1, ce_b1, h1,
                                                           NTOK, 256, 1024);
    }
    gemm_kernel<false><<<dim3(4, 128), 256>>>(h1, ce_w2, ce_b2, change, NTOK, 512, 256);

    // GRU recurrence
    reset_kernel<<<1, 256>>>();
    gru_kernel<<<GRU_CTAS, 256>>>(xg, W_hh, b_hh, memc);

    // fusion path: fh = gelu([emb,s,m,l,mem] @ fu_w1^T + b); fused = fh @ fu_w2^T + b
    {
        SegPtrs sp{};
        sp.p[0] = emb; sp.p[1] = sctx; sp.p[2] = mctx; sp.p[3] = lctx; sp.p[4] = memc;
        seg_gemm_kernel<true, false><<<dim3(8, 128), 256>>>(sp, fu_w1, fu_b1, fh,
                                                            NTOK, 1024, 2560);
    }
    gemm_kernel<false><<<dim3(4, 128), 256>>>(fh, fu_w2, fu_b2, fused, NTOK, 512, 1024);

    // out = LN(emb + fused + change)
    final_kernel<<<NTOK, 512>>>(emb, fused, change, ln_g, ln_b, (float*)d_out);
}